// round 14
// baseline (speedup 1.0000x reference)
#include <cuda_runtime.h>
#include <cuda_fp16.h>
#include <cstdint>

#define N_T 32
#define NF  17
#define SIZE 1024
#define PQ  1048576

// GEMM tiling: 128x128 CTA tile, 4 warps of 64x64, K=1024
#define BM 128
#define BN 128
#define KC 64
#define NC (SIZE / KC)      // 16 chunks
#define NSTAGE 3
#define STAGE_BYTES 32768   // A(16K)+B(16K)
#define OFF_A 0
#define OFF_B 16384
#define NPROD 47            // 15 freqs x 3 products + k=0,16 x 1 product

// Compile-time twiddles (fold to FFMA immediates under full unroll)
__device__ constexpr float TWC[32] = {
     1.00000000f,  0.98078528f,  0.92387953f,  0.83146961f,
     0.70710678f,  0.55557023f,  0.38268343f,  0.19509032f,
     0.00000000f, -0.19509032f, -0.38268343f, -0.55557023f,
    -0.70710678f, -0.83146961f, -0.92387953f, -0.98078528f,
    -1.00000000f, -0.98078528f, -0.92387953f, -0.83146961f,
    -0.70710678f, -0.55557023f, -0.38268343f, -0.19509032f,
     0.00000000f,  0.19509032f,  0.38268343f,  0.55557023f,
     0.70710678f,  0.83146961f,  0.92387953f,  0.98078528f
};
__device__ constexpr float TWS[32] = {
     0.00000000f,  0.19509032f,  0.38268343f,  0.55557023f,
     0.70710678f,  0.83146961f,  0.92387953f,  0.98078528f,
     1.00000000f,  0.98078528f,  0.92387953f,  0.83146961f,
     0.70710678f,  0.55557023f,  0.38268343f,  0.19509032f,
     0.00000000f, -0.19509032f, -0.38268343f, -0.55557023f,
    -0.70710678f, -0.83146961f, -0.92387953f, -0.98078528f,
    -1.00000000f, -0.98078528f, -0.92387953f, -0.83146961f,
    -0.70710678f, -0.55557023f, -0.38268343f, -0.19509032f
};

// ---------------------------------------------------------------------------
// Device scratch
// ---------------------------------------------------------------------------
__device__ __half g_A[(size_t)NF * 3 * PQ];   // [k][plane][p][q]
__device__ __half g_B[(size_t)NF * 3 * PQ];   // [k][plane][m][q] (B^T K-major)
__device__ __half g_P[(size_t)NF * 3 * PQ];   // [k][prod][p][m]  (fp16 products)

// ---------------------------------------------------------------------------
// PTX helpers (baseline PTX only)
// ---------------------------------------------------------------------------
__device__ __forceinline__ uint32_t smem_u32(const void* p) {
    uint32_t a;
    asm("{ .reg .u64 t; cvta.to.shared.u64 t, %1; cvt.u32.u64 %0, t; }"
        : "=r"(a) : "l"(p));
    return a;
}

__device__ __forceinline__ void cpa16(uint32_t dst, const void* src) {
    asm volatile("cp.async.cg.shared.global [%0], [%1], 16;" :: "r"(dst), "l"(src) : "memory");
}
#define CP_COMMIT() asm volatile("cp.async.commit_group;" ::: "memory")
#define CP_WAIT1()  asm volatile("cp.async.wait_group 1;"  ::: "memory")

__device__ __forceinline__ void ldsm4(uint32_t* r, uint32_t addr) {
    asm volatile("ldmatrix.sync.aligned.m8n8.x4.shared.b16 {%0,%1,%2,%3}, [%4];"
                 : "=r"(r[0]), "=r"(r[1]), "=r"(r[2]), "=r"(r[3]) : "r"(addr));
}

__device__ __forceinline__ void mma16816(float* d, const uint32_t* a, const uint32_t* b) {
    asm volatile("mma.sync.aligned.m16n8k16.row.col.f32.f16.f16.f32 "
                 "{%0,%1,%2,%3}, {%4,%5,%6,%7}, {%8,%9}, {%0,%1,%2,%3};"
                 : "+f"(d[0]), "+f"(d[1]), "+f"(d[2]), "+f"(d[3])
                 : "r"(a[0]), "r"(a[1]), "r"(a[2]), "r"(a[3]), "r"(b[0]), "r"(b[1]));
}

// ---------------------------------------------------------------------------
// Prep A: DFT-32 of weights -> fp16 planes Ar, Ai, As=Ar+Ai per freq
// ---------------------------------------------------------------------------
__global__ __launch_bounds__(256) void prepA(const float* __restrict__ w) {
    int idx = blockIdx.x * 256 + threadIdx.x;

    float v[N_T];
    #pragma unroll
    for (int n = 0; n < N_T; n++) v[n] = w[n * PQ + idx];

    float e[16], o[16];
    #pragma unroll
    for (int n = 0; n < 16; n++) { e[n] = v[n] + v[n + 16]; o[n] = v[n] - v[n + 16]; }

    #pragma unroll
    for (int k = 0; k < NF; k++) {
        float re = 0.0f, im = 0.0f;
        #pragma unroll
        for (int n = 0; n < 16; n++) {
            float s = (k & 1) ? o[n] : e[n];
            re += s * TWC[(k * n) & 31];
            im -= s * TWS[(k * n) & 31];
        }
        size_t base = (size_t)(k * 3) * PQ + idx;
        g_A[base] = __float2half(re);
        if (k != 0 && k != 16) {
            g_A[base + PQ]     = __float2half(im);
            g_A[base + 2 * PQ] = __float2half(re + im);
        }
    }
}

// ---------------------------------------------------------------------------
// Prep B: DFT-32 of x -> fp16 B^T planes (K-major [m][q]): Br, Bi, Bs
// ---------------------------------------------------------------------------
__global__ __launch_bounds__(1024) void prepB(const float* __restrict__ x) {
    __shared__ __half sre[32][33], sim[32][33];
    int t = threadIdx.x;

    int bm = blockIdx.x & 31, bq = blockIdx.x >> 5;
    int lm = t & 31, lq = t >> 5;
    int q = bq * 32 + lq, m = bm * 32 + lm;

    float v[N_T];
    #pragma unroll
    for (int n = 0; n < N_T; n++) v[n] = x[(size_t)n * PQ + q * 1024 + m];

    float e[16], o[16];
    #pragma unroll
    for (int n = 0; n < 16; n++) { e[n] = v[n] + v[n + 16]; o[n] = v[n] - v[n + 16]; }

    #pragma unroll 1
    for (int k = 0; k < NF; k++) {
        float re = 0.0f, im = 0.0f;
        if (k & 1) {
            #pragma unroll
            for (int n = 0; n < 16; n++) {
                re += o[n] * TWC[(k * n) & 31];
                im -= o[n] * TWS[(k * n) & 31];
            }
        } else {
            #pragma unroll
            for (int n = 0; n < 16; n++) {
                re += e[n] * TWC[(k * n) & 31];
                im -= e[n] * TWS[(k * n) & 31];
            }
        }

        __syncthreads();
        sre[lq][lm] = __float2half(re);
        sim[lq][lm] = __float2half(im);
        __syncthreads();

        size_t rowbase = (size_t)(k * 3) * PQ + (size_t)(bm * 32 + lq) * 1024 + bq * 32 + lm;
        __half r2 = sre[lm][lq], i2 = sim[lm][lq];
        g_B[rowbase] = r2;
        if (k != 0 && k != 16) {
            g_B[rowbase + PQ]     = i2;
            g_B[rowbase + 2 * PQ] = __hadd(r2, i2);
        }
    }
}

// ---------------------------------------------------------------------------
// fp16 GEMM per product: P[z] = A[z] * B[z]^T, 1024^3, fp32 acc, fp16 out.
// 128x128 CTA tile, 4 warps (2m x 2n) of 64x64, 3-stage cp.async, 2 CTA/SM.
// ---------------------------------------------------------------------------
__global__ __launch_bounds__(128, 2) void tgemm() {
    extern __shared__ char dynsmem[];
    uint32_t sbase = (smem_u32(dynsmem) + 1023u) & ~1023u;

    const int t = threadIdx.x;
    const int lane = t & 31;
    const int wid = t >> 5;
    const int m_warp = (wid >> 1) * 64, n_warp = (wid & 1) * 64;

    int z = blockIdx.z, k, plane;
    if (z < 45) { k = 1 + z / 3; plane = z % 3; }
    else { k = (z == 45) ? 0 : 16; plane = 0; }

    const size_t zoff = (size_t)(k * 3 + plane) * PQ;
    const size_t aoff = zoff + (size_t)blockIdx.y * BM * 1024;
    const size_t boff = zoff + (size_t)blockIdx.x * BN * 1024;

    const int rowA_off = (lane & 7) + ((lane >> 3) & 1) * 8;
    const int kselA    = lane >> 4;
    const int rowB_off = (lane & 7) + ((lane >> 4) & 1) * 8;
    const int kselB    = (lane >> 3) & 1;

    auto copy_chunk = [&](int c) {
        uint32_t sb = sbase + (uint32_t)(c % NSTAGE) * STAGE_BYTES;
        size_t kcol = (size_t)c * KC;
        #pragma unroll
        for (int i = 0; i < 8; i++) {
            int u = t + i * 128;
            int r = u >> 3, c16 = u & 7;
            uint32_t sw = (uint32_t)(r * 128 + ((c16 ^ (r & 7)) << 4));
            cpa16(sb + OFF_A + sw, g_A + aoff + (size_t)r * 1024 + kcol + c16 * 8);
            cpa16(sb + OFF_B + sw, g_B + boff + (size_t)r * 1024 + kcol + c16 * 8);
        }
    };

    float acc[4][8][4];
    #pragma unroll
    for (int i = 0; i < 4; i++)
        #pragma unroll
        for (int j = 0; j < 8; j++)
            #pragma unroll
            for (int r = 0; r < 4; r++) acc[i][j][r] = 0.0f;

    copy_chunk(0); CP_COMMIT();
    copy_chunk(1); CP_COMMIT();

    for (int c = 0; c < NC; c++) {
        CP_WAIT1();
        __syncthreads();
        uint32_t sb = sbase + (uint32_t)(c % NSTAGE) * STAGE_BYTES;

        #pragma unroll
        for (int ks = 0; ks < 4; ks++) {
            uint32_t ah[4][4], bh[4][4];
            #pragma unroll
            for (int mt = 0; mt < 4; mt++) {
                int row = m_warp + mt * 16 + rowA_off;
                int kch = ks * 2 + kselA;
                ldsm4(ah[mt], sb + OFF_A + (uint32_t)(row * 128 + ((kch ^ (row & 7)) << 4)));
            }
            #pragma unroll
            for (int nt2 = 0; nt2 < 4; nt2++) {
                int row = n_warp + nt2 * 16 + rowB_off;
                int kch = ks * 2 + kselB;
                ldsm4(bh[nt2], sb + OFF_B + (uint32_t)(row * 128 + ((kch ^ (row & 7)) << 4)));
            }
            #pragma unroll
            for (int mt = 0; mt < 4; mt++) {
                #pragma unroll
                for (int nt = 0; nt < 8; nt++) {
                    mma16816(acc[mt][nt], ah[mt], &bh[nt >> 1][(nt & 1) * 2]);
                }
            }
        }
        if (c + 2 < NC) copy_chunk(c + 2);
        CP_COMMIT();
    }

    // epilogue: fp16 output (half2 stores)
    const int qd = lane >> 2, rr = lane & 3;
    __half* dstbase = g_P + zoff + (size_t)blockIdx.y * BM * 1024 + blockIdx.x * BN;
    #pragma unroll
    for (int mt = 0; mt < 4; mt++) {
        #pragma unroll
        for (int half = 0; half < 2; half++) {
            int row = m_warp + mt * 16 + qd + half * 8;
            __half* dst = dstbase + (size_t)row * 1024;
            #pragma unroll
            for (int nt = 0; nt < 8; nt++) {
                int n = n_warp + nt * 8 + rr * 2;
                *reinterpret_cast<__half2*>(dst + n) =
                    __floats2half2_rn(acc[mt][nt][half * 2], acc[mt][nt][half * 2 + 1]);
            }
        }
    }
}

// ---------------------------------------------------------------------------
// Karatsuba combine + inverse DFT-32 + bias (batched loads),
// occupancy-capped to 4 CTAs/SM (<=64 regs) for better latency hiding.
// Cre = P1 - P2 ; Cim = P3 - P1 - P2 ; k=0,16: C = (P1, 0)
// out[n] = E+O, out[n+16] = E-O, n in [0,16)
// ---------------------------------------------------------------------------
__global__ __launch_bounds__(256, 4) void ifft32_bias_kernel(const float* __restrict__ bias,
                                                             float* __restrict__ out) {
    int idx = blockIdx.x * 256 + threadIdx.x;

    float cvx[NF], cvy[NF];
    cvx[0]  = __half2float(g_P[(size_t)0 * PQ + idx]);          cvy[0]  = 0.0f;
    cvx[16] = __half2float(g_P[(size_t)(16 * 3) * PQ + idx]);   cvy[16] = 0.0f;
    #pragma unroll
    for (int k = 1; k < 16; k++) {
        size_t base = (size_t)(k * 3) * PQ + idx;
        float p1 = __half2float(g_P[base]);
        float p2 = __half2float(g_P[base + PQ]);
        float p3 = __half2float(g_P[base + 2 * PQ]);
        cvx[k] = 2.0f * (p1 - p2);
        cvy[k] = 2.0f * (p3 - p1 - p2);
    }

    float b = bias[idx];

    #pragma unroll
    for (int n = 0; n < 16; n++) {
        float E = cvx[0] + ((n & 1) ? -cvx[16] : cvx[16]);
        float O = 0.0f;
        #pragma unroll
        for (int k = 1; k < 16; k++) {
            float term = cvx[k] * TWC[(k * n) & 31] - cvy[k] * TWS[(k * n) & 31];
            if (k & 1) O += term; else E += term;
        }
        out[n * PQ + idx]        = (E + O) * (1.0f / 32.0f) + b;
        out[(n + 16) * PQ + idx] = (E - O) * (1.0f / 32.0f) + b;
    }
}

// ---------------------------------------------------------------------------
// Launch
// ---------------------------------------------------------------------------
extern "C" void kernel_launch(void* const* d_in, const int* in_sizes, int n_in,
                              void* d_out, int out_size) {
    const float* x    = (const float*)d_in[0];
    const float* w    = (const float*)d_in[1];
    const float* bias = (const float*)d_in[2];
    float*       out  = (float*)d_out;

    cudaFuncSetAttribute(tgemm, cudaFuncAttributeMaxDynamicSharedMemorySize, 99328);

    prepA<<<4096, 256>>>(w);
    prepB<<<1024, 1024>>>(x);

    dim3 gg(SIZE / BN, SIZE / BM, NPROD);   // (8, 8, 47)
    tgemm<<<gg, 128, 99328>>>();

    ifft32_bias_kernel<<<4096, 256>>>(bias, out);
}

// round 15
// speedup vs baseline: 1.0134x; 1.0134x over previous
#include <cuda_runtime.h>
#include <cuda_fp16.h>
#include <cstdint>

#define N_T 32
#define NF  17
#define SIZE 1024
#define PQ  1048576

// GEMM tiling: 128x128 CTA tile, 4 warps of 64x64, K=1024
#define BM 128
#define BN 128
#define KC 64
#define NC (SIZE / KC)      // 16 chunks
#define NSTAGE 3
#define STAGE_BYTES 32768   // A(16K)+B(16K)
#define OFF_A 0
#define OFF_B 16384
#define NPROD 47            // 15 freqs x 3 products + k=0,16 x 1 product

// Compile-time twiddles (fold to FFMA immediates under full unroll)
__device__ constexpr float TWC[32] = {
     1.00000000f,  0.98078528f,  0.92387953f,  0.83146961f,
     0.70710678f,  0.55557023f,  0.38268343f,  0.19509032f,
     0.00000000f, -0.19509032f, -0.38268343f, -0.55557023f,
    -0.70710678f, -0.83146961f, -0.92387953f, -0.98078528f,
    -1.00000000f, -0.98078528f, -0.92387953f, -0.83146961f,
    -0.70710678f, -0.55557023f, -0.38268343f, -0.19509032f,
     0.00000000f,  0.19509032f,  0.38268343f,  0.55557023f,
     0.70710678f,  0.83146961f,  0.92387953f,  0.98078528f
};
__device__ constexpr float TWS[32] = {
     0.00000000f,  0.19509032f,  0.38268343f,  0.55557023f,
     0.70710678f,  0.83146961f,  0.92387953f,  0.98078528f,
     1.00000000f,  0.98078528f,  0.92387953f,  0.83146961f,
     0.70710678f,  0.55557023f,  0.38268343f,  0.19509032f,
     0.00000000f, -0.19509032f, -0.38268343f, -0.55557023f,
    -0.70710678f, -0.83146961f, -0.92387953f, -0.98078528f,
    -1.00000000f, -0.98078528f, -0.92387953f, -0.83146961f,
    -0.70710678f, -0.55557023f, -0.38268343f, -0.19509032f
};

// ---------------------------------------------------------------------------
// Device scratch
// ---------------------------------------------------------------------------
__device__ __half g_A[(size_t)NF * 3 * PQ];   // [k][plane][p][q]
__device__ __half g_B[(size_t)NF * 3 * PQ];   // [k][plane][m][q] (B^T K-major)
__device__ __half g_P[(size_t)NF * 3 * PQ];   // [k][prod][p][m]  (fp16 products)

// ---------------------------------------------------------------------------
// PTX helpers (baseline PTX only)
// ---------------------------------------------------------------------------
__device__ __forceinline__ uint32_t smem_u32(const void* p) {
    uint32_t a;
    asm("{ .reg .u64 t; cvta.to.shared.u64 t, %1; cvt.u32.u64 %0, t; }"
        : "=r"(a) : "l"(p));
    return a;
}

__device__ __forceinline__ void cpa16(uint32_t dst, const void* src) {
    asm volatile("cp.async.cg.shared.global [%0], [%1], 16;" :: "r"(dst), "l"(src) : "memory");
}
#define CP_COMMIT() asm volatile("cp.async.commit_group;" ::: "memory")
#define CP_WAIT1()  asm volatile("cp.async.wait_group 1;"  ::: "memory")

__device__ __forceinline__ void ldsm4(uint32_t* r, uint32_t addr) {
    asm volatile("ldmatrix.sync.aligned.m8n8.x4.shared.b16 {%0,%1,%2,%3}, [%4];"
                 : "=r"(r[0]), "=r"(r[1]), "=r"(r[2]), "=r"(r[3]) : "r"(addr));
}

__device__ __forceinline__ void mma16816(float* d, const uint32_t* a, const uint32_t* b) {
    asm volatile("mma.sync.aligned.m16n8k16.row.col.f32.f16.f16.f32 "
                 "{%0,%1,%2,%3}, {%4,%5,%6,%7}, {%8,%9}, {%0,%1,%2,%3};"
                 : "+f"(d[0]), "+f"(d[1]), "+f"(d[2]), "+f"(d[3])
                 : "r"(a[0]), "r"(a[1]), "r"(a[2]), "r"(a[3]), "r"(b[0]), "r"(b[1]));
}

// ---------------------------------------------------------------------------
// Prep A: DFT-32 of weights -> fp16 planes Ar, Ai, As=Ar+Ai per freq
// ---------------------------------------------------------------------------
__global__ __launch_bounds__(256) void prepA(const float* __restrict__ w) {
    int idx = blockIdx.x * 256 + threadIdx.x;

    float v[N_T];
    #pragma unroll
    for (int n = 0; n < N_T; n++) v[n] = w[n * PQ + idx];

    float e[16], o[16];
    #pragma unroll
    for (int n = 0; n < 16; n++) { e[n] = v[n] + v[n + 16]; o[n] = v[n] - v[n + 16]; }

    #pragma unroll
    for (int k = 0; k < NF; k++) {
        float re = 0.0f, im = 0.0f;
        #pragma unroll
        for (int n = 0; n < 16; n++) {
            float s = (k & 1) ? o[n] : e[n];
            re += s * TWC[(k * n) & 31];
            im -= s * TWS[(k * n) & 31];
        }
        size_t base = (size_t)(k * 3) * PQ + idx;
        g_A[base] = __float2half(re);
        if (k != 0 && k != 16) {
            g_A[base + PQ]     = __float2half(im);
            g_A[base + 2 * PQ] = __float2half(re + im);
        }
    }
}

// ---------------------------------------------------------------------------
// Prep B: DFT-32 of x -> fp16 B^T planes (K-major [m][q]): Br, Bi, Bs
// Double-buffered transpose smem: one __syncthreads per k instead of two.
// ---------------------------------------------------------------------------
__global__ __launch_bounds__(1024) void prepB(const float* __restrict__ x) {
    __shared__ __half sre[2][32][33], sim[2][32][33];
    int t = threadIdx.x;

    int bm = blockIdx.x & 31, bq = blockIdx.x >> 5;
    int lm = t & 31, lq = t >> 5;
    int q = bq * 32 + lq, m = bm * 32 + lm;

    float v[N_T];
    #pragma unroll
    for (int n = 0; n < N_T; n++) v[n] = x[(size_t)n * PQ + q * 1024 + m];

    float e[16], o[16];
    #pragma unroll
    for (int n = 0; n < 16; n++) { e[n] = v[n] + v[n + 16]; o[n] = v[n] - v[n + 16]; }

    #pragma unroll 1
    for (int k = 0; k < NF; k++) {
        int buf = k & 1;
        float re = 0.0f, im = 0.0f;
        if (k & 1) {
            #pragma unroll
            for (int n = 0; n < 16; n++) {
                re += o[n] * TWC[(k * n) & 31];
                im -= o[n] * TWS[(k * n) & 31];
            }
        } else {
            #pragma unroll
            for (int n = 0; n < 16; n++) {
                re += e[n] * TWC[(k * n) & 31];
                im -= e[n] * TWS[(k * n) & 31];
            }
        }

        // writes go to buf, which was last read two iterations ago (same parity);
        // the sync below (and the one in iteration k-1) orders reuse safely:
        // buffer `buf` was read right after the sync in iteration k-2, and all
        // threads passed the k-1 sync since then.
        sre[buf][lq][lm] = __float2half(re);
        sim[buf][lq][lm] = __float2half(im);
        __syncthreads();

        size_t rowbase = (size_t)(k * 3) * PQ + (size_t)(bm * 32 + lq) * 1024 + bq * 32 + lm;
        __half r2 = sre[buf][lm][lq], i2 = sim[buf][lm][lq];
        g_B[rowbase] = r2;
        if (k != 0 && k != 16) {
            g_B[rowbase + PQ]     = i2;
            g_B[rowbase + 2 * PQ] = __hadd(r2, i2);
        }
    }
}

// ---------------------------------------------------------------------------
// fp16 GEMM per product: P[z] = A[z] * B[z]^T, 1024^3, fp32 acc, fp16 out.
// 128x128 CTA tile, 4 warps (2m x 2n) of 64x64, 3-stage cp.async, 2 CTA/SM.
// ---------------------------------------------------------------------------
__global__ __launch_bounds__(128, 2) void tgemm() {
    extern __shared__ char dynsmem[];
    uint32_t sbase = (smem_u32(dynsmem) + 1023u) & ~1023u;

    const int t = threadIdx.x;
    const int lane = t & 31;
    const int wid = t >> 5;
    const int m_warp = (wid >> 1) * 64, n_warp = (wid & 1) * 64;

    int z = blockIdx.z, k, plane;
    if (z < 45) { k = 1 + z / 3; plane = z % 3; }
    else { k = (z == 45) ? 0 : 16; plane = 0; }

    const size_t zoff = (size_t)(k * 3 + plane) * PQ;
    const size_t aoff = zoff + (size_t)blockIdx.y * BM * 1024;
    const size_t boff = zoff + (size_t)blockIdx.x * BN * 1024;

    const int rowA_off = (lane & 7) + ((lane >> 3) & 1) * 8;
    const int kselA    = lane >> 4;
    const int rowB_off = (lane & 7) + ((lane >> 4) & 1) * 8;
    const int kselB    = (lane >> 3) & 1;

    auto copy_chunk = [&](int c) {
        uint32_t sb = sbase + (uint32_t)(c % NSTAGE) * STAGE_BYTES;
        size_t kcol = (size_t)c * KC;
        #pragma unroll
        for (int i = 0; i < 8; i++) {
            int u = t + i * 128;
            int r = u >> 3, c16 = u & 7;
            uint32_t sw = (uint32_t)(r * 128 + ((c16 ^ (r & 7)) << 4));
            cpa16(sb + OFF_A + sw, g_A + aoff + (size_t)r * 1024 + kcol + c16 * 8);
            cpa16(sb + OFF_B + sw, g_B + boff + (size_t)r * 1024 + kcol + c16 * 8);
        }
    };

    float acc[4][8][4];
    #pragma unroll
    for (int i = 0; i < 4; i++)
        #pragma unroll
        for (int j = 0; j < 8; j++)
            #pragma unroll
            for (int r = 0; r < 4; r++) acc[i][j][r] = 0.0f;

    copy_chunk(0); CP_COMMIT();
    copy_chunk(1); CP_COMMIT();

    for (int c = 0; c < NC; c++) {
        CP_WAIT1();
        __syncthreads();
        uint32_t sb = sbase + (uint32_t)(c % NSTAGE) * STAGE_BYTES;

        #pragma unroll
        for (int ks = 0; ks < 4; ks++) {
            uint32_t ah[4][4], bh[4][4];
            #pragma unroll
            for (int mt = 0; mt < 4; mt++) {
                int row = m_warp + mt * 16 + rowA_off;
                int kch = ks * 2 + kselA;
                ldsm4(ah[mt], sb + OFF_A + (uint32_t)(row * 128 + ((kch ^ (row & 7)) << 4)));
            }
            #pragma unroll
            for (int nt2 = 0; nt2 < 4; nt2++) {
                int row = n_warp + nt2 * 16 + rowB_off;
                int kch = ks * 2 + kselB;
                ldsm4(bh[nt2], sb + OFF_B + (uint32_t)(row * 128 + ((kch ^ (row & 7)) << 4)));
            }
            #pragma unroll
            for (int mt = 0; mt < 4; mt++) {
                #pragma unroll
                for (int nt = 0; nt < 8; nt++) {
                    mma16816(acc[mt][nt], ah[mt], &bh[nt >> 1][(nt & 1) * 2]);
                }
            }
        }
        if (c + 2 < NC) copy_chunk(c + 2);
        CP_COMMIT();
    }

    // epilogue: fp16 output (half2 stores)
    const int qd = lane >> 2, rr = lane & 3;
    __half* dstbase = g_P + zoff + (size_t)blockIdx.y * BM * 1024 + blockIdx.x * BN;
    #pragma unroll
    for (int mt = 0; mt < 4; mt++) {
        #pragma unroll
        for (int half = 0; half < 2; half++) {
            int row = m_warp + mt * 16 + qd + half * 8;
            __half* dst = dstbase + (size_t)row * 1024;
            #pragma unroll
            for (int nt = 0; nt < 8; nt++) {
                int n = n_warp + nt * 8 + rr * 2;
                *reinterpret_cast<__half2*>(dst + n) =
                    __floats2half2_rn(acc[mt][nt][half * 2], acc[mt][nt][half * 2 + 1]);
            }
        }
    }
}

// ---------------------------------------------------------------------------
// Karatsuba combine + inverse DFT-32 + bias (batched loads),
// occupancy-capped to 3 CTAs/SM (80 regs — measured optimum).
// Bias folded into E-init: out = (E' +- O)/32 with E' = E + 32b.
// ---------------------------------------------------------------------------
__global__ __launch_bounds__(256, 3) void ifft32_bias_kernel(const float* __restrict__ bias,
                                                             float* __restrict__ out) {
    int idx = blockIdx.x * 256 + threadIdx.x;

    float cvx[NF], cvy[NF];
    cvx[0]  = __half2float(g_P[(size_t)0 * PQ + idx]);
    cvx[16] = __half2float(g_P[(size_t)(16 * 3) * PQ + idx]);
    #pragma unroll
    for (int k = 1; k < 16; k++) {
        size_t base = (size_t)(k * 3) * PQ + idx;
        float p1 = __half2float(g_P[base]);
        float p2 = __half2float(g_P[base + PQ]);
        float p3 = __half2float(g_P[base + 2 * PQ]);
        cvx[k] = 2.0f * (p1 - p2);
        cvy[k] = 2.0f * (p3 - p1 - p2);
    }

    float c0 = fmaf(32.0f, bias[idx], cvx[0]);   // fold bias: E' = E + 32b

    #pragma unroll
    for (int n = 0; n < 16; n++) {
        float E = c0 + ((n & 1) ? -cvx[16] : cvx[16]);
        float O = 0.0f;
        #pragma unroll
        for (int k = 1; k < 16; k++) {
            float term = cvx[k] * TWC[(k * n) & 31] - cvy[k] * TWS[(k * n) & 31];
            if (k & 1) O += term; else E += term;
        }
        out[n * PQ + idx]        = (E + O) * (1.0f / 32.0f);
        out[(n + 16) * PQ + idx] = (E - O) * (1.0f / 32.0f);
    }
}

// ---------------------------------------------------------------------------
// Launch
// ---------------------------------------------------------------------------
extern "C" void kernel_launch(void* const* d_in, const int* in_sizes, int n_in,
                              void* d_out, int out_size) {
    const float* x    = (const float*)d_in[0];
    const float* w    = (const float*)d_in[1];
    const float* bias = (const float*)d_in[2];
    float*       out  = (float*)d_out;

    cudaFuncSetAttribute(tgemm, cudaFuncAttributeMaxDynamicSharedMemorySize, 99328);

    prepA<<<4096, 256>>>(w);
    prepB<<<1024, 1024>>>(x);

    dim3 gg(SIZE / BN, SIZE / BM, NPROD);   // (8, 8, 47)
    tgemm<<<gg, 128, 99328>>>();

    ifft32_bias_kernel<<<4096, 256>>>(bias, out);
}